// round 1
// baseline (speedup 1.0000x reference)
#include <cuda_runtime.h>
#include <cstdint>

// Depthwise 3D conv 3x3x3, SAME, stride 1.
// x: (N=4, D=16, H=112, W=112, C=64) f32, NDHWC
// w: (3,3,3,1,64) f32  -> idx ((kd*3+kh)*3+kw)*64 + c
// out: same shape as x.

#define N_  4
#define D_  16
#define H_  112
#define W_  112
#define C_  64
#define WPT 8          // outputs per thread along W
#define CG  16         // channel groups of 4 (float4) -> 16 threads span C
#define HY  8          // h rows per block (threadIdx.y)

__device__ __forceinline__ unsigned long long ffma2(unsigned long long a,
                                                    unsigned long long b,
                                                    unsigned long long c) {
    unsigned long long d;
    asm("fma.rn.f32x2 %0, %1, %2, %3;" : "=l"(d) : "l"(a), "l"(b), "l"(c));
    return d;
}

__global__ void __launch_bounds__(CG * HY, 2)
dwconv3d_kernel(const float* __restrict__ x,
                const float* __restrict__ wgt,
                float* __restrict__ out) {
    __shared__ float sw[27 * C_];

    const int tid = threadIdx.y * CG + threadIdx.x;  // 0..127
    // Stage weights (1728 floats) into smem.
    for (int i = tid; i < 27 * C_; i += CG * HY) sw[i] = wgt[i];
    __syncthreads();

    const int c4 = threadIdx.x;                       // 0..15 (float4 group)
    const int h  = blockIdx.y * HY + threadIdx.y;     // 0..111
    const int w0 = blockIdx.x * WPT;                  // 0,8,...,104
    const int nd = blockIdx.z;                        // 0..63
    const int n  = nd / D_;
    const int d  = nd % D_;

    // accumulators: WPT outputs x 4 channels, as 2x f32x2 packs each
    unsigned long long accLo[WPT], accHi[WPT];
#pragma unroll
    for (int i = 0; i < WPT; i++) { accLo[i] = 0ull; accHi[i] = 0ull; }

    const ulonglong2* __restrict__ xp = reinterpret_cast<const ulonglong2*>(x);
    const ulonglong2* __restrict__ swp = reinterpret_cast<const ulonglong2*>(sw);

    const ulonglong2 zero = make_ulonglong2(0ull, 0ull);

#pragma unroll
    for (int kd = 0; kd < 3; kd++) {
        const int zd = d + kd - 1;
        if (zd < 0 || zd >= D_) continue;
#pragma unroll
        for (int kh = 0; kh < 3; kh++) {
            const int zh = h + kh - 1;
            if (zh < 0 || zh >= H_) continue;

            // row base in ull2 units: voxel(n,zd,zh,w=0)*16 + c4
            const size_t rowBase =
                ((((size_t)n * D_ + zd) * H_ + zh) * W_) * (C_ / 4) + c4;
            const ulonglong2* rowp = xp + rowBase;

            // weight taps for this (kd,kh): kw = 0,1,2
            const int wb = (kd * 3 + kh) * 3;
            const ulonglong2 wk0 = swp[(wb + 0) * (C_ / 4) + c4];
            const ulonglong2 wk1 = swp[(wb + 1) * (C_ / 4) + c4];
            const ulonglong2 wk2 = swp[(wb + 2) * (C_ / 4) + c4];

            // sliding window over zw = w0-1 .. w0+WPT
            ulonglong2 a = (w0 > 0) ? rowp[(size_t)(w0 - 1) * (C_ / 4)] : zero;
            ulonglong2 b = rowp[(size_t)w0 * (C_ / 4)];
#pragma unroll
            for (int i = 0; i < WPT; i++) {
                const int zw = w0 + i + 1;
                ulonglong2 c =
                    (zw < W_) ? rowp[(size_t)zw * (C_ / 4)] : zero;

                accLo[i] = ffma2(a.x, wk0.x, accLo[i]);
                accHi[i] = ffma2(a.y, wk0.y, accHi[i]);
                accLo[i] = ffma2(b.x, wk1.x, accLo[i]);
                accHi[i] = ffma2(b.y, wk1.y, accHi[i]);
                accLo[i] = ffma2(c.x, wk2.x, accLo[i]);
                accHi[i] = ffma2(c.y, wk2.y, accHi[i]);

                a = b;
                b = c;
            }
        }
    }

    // store
    ulonglong2* __restrict__ op =
        reinterpret_cast<ulonglong2*>(out) +
        ((((size_t)n * D_ + d) * H_ + h) * W_ + w0) * (C_ / 4) + c4;
#pragma unroll
    for (int i = 0; i < WPT; i++) {
        op[(size_t)i * (C_ / 4)] = make_ulonglong2(accLo[i], accHi[i]);
    }
}

extern "C" void kernel_launch(void* const* d_in, const int* in_sizes, int n_in,
                              void* d_out, int out_size) {
    const float* x = (const float*)d_in[0];
    const float* w = (const float*)d_in[1];
    float* o = (float*)d_out;

    dim3 block(CG, HY, 1);                       // 128 threads
    dim3 grid(W_ / WPT, H_ / HY, N_ * D_);       // 14 x 14 x 64
    dwconv3d_kernel<<<grid, block>>>(x, w, o);
}

// round 2
// speedup vs baseline: 1.4026x; 1.4026x over previous
#include <cuda_runtime.h>
#include <cstdint>

// Depthwise 3D conv 3x3x3, SAME, stride 1.
// x: (N=4, D=16, H=112, W=112, C=64) f32, NDHWC
// w: (3,3,3,1,64) f32 -> idx ((kd*3+kh)*3+kw)*64 + c
//
// Layout: thread owns 2 channels (one ull / f32x2 pack), 8 w-outputs, 2 h-rows.
// Warp: threadIdx.x = 0..31 spans all 64 channels -> 256B coalesced row loads.
// h-reuse: rows h0-1..h0+2 loaded once, feed both h0 and h0+1 outputs (1.5x
// fewer L1 bytes than the 1-row version). All math via packed fma.rn.f32x2.

#define N_  4
#define D_  16
#define H_  112
#define W_  112
#define C_  64
#define WPT 8
#define CS  (C_ / 2)   // 32 ull per spatial position

__device__ __forceinline__ unsigned long long ffma2(unsigned long long a,
                                                    unsigned long long b,
                                                    unsigned long long c) {
    unsigned long long d;
    asm("fma.rn.f32x2 %0, %1, %2, %3;" : "=l"(d) : "l"(a), "l"(b), "l"(c));
    return d;
}

__global__ void __launch_bounds__(128)
dwconv3d_kernel(const float* __restrict__ x,
                const float* __restrict__ wgt,
                float* __restrict__ out) {
    __shared__ float swf[27 * C_];

    const int tid = threadIdx.y * 32 + threadIdx.x;  // 0..127
    for (int i = tid; i < 27 * C_ / 4; i += 128)
        reinterpret_cast<float4*>(swf)[i] =
            reinterpret_cast<const float4*>(wgt)[i];
    __syncthreads();

    const unsigned long long* __restrict__ swp =
        reinterpret_cast<const unsigned long long*>(swf);

    const int tx = threadIdx.x;                       // channel pair 0..31
    const int h0 = blockIdx.y * 8 + threadIdx.y * 2;  // even rows 0..110
    const int w0 = blockIdx.x * WPT;                  // 0..104
    const int nd = blockIdx.z;
    const int n  = nd >> 4;
    const int d  = nd & 15;

    unsigned long long acc0[WPT], acc1[WPT];
#pragma unroll
    for (int i = 0; i < WPT; i++) { acc0[i] = 0ull; acc1[i] = 0ull; }

    const unsigned long long* __restrict__ xp =
        reinterpret_cast<const unsigned long long*>(x);

#pragma unroll
    for (int kd = 0; kd < 3; kd++) {
        const int zd = d + kd - 1;
        if ((unsigned)zd >= D_) continue;

#pragma unroll
        for (int r = 0; r < 4; r++) {          // rows h0-1 .. h0+2
            const int zh = h0 - 1 + r;
            if ((unsigned)zh >= H_) continue;
            const bool J0 = (r <= 2);          // contributes to output h0 (kh=r)
            const bool J1 = (r >= 1);          // contributes to output h0+1 (kh=r-1)

            const unsigned long long* __restrict__ rowp =
                xp + ((((n * D_ + zd) * H_ + zh) * W_) * CS + tx);

            unsigned long long w00 = 0, w01 = 0, w02 = 0;
            unsigned long long w10 = 0, w11 = 0, w12 = 0;
            if (J0) {
                const int b0 = (kd * 9 + r * 3) * CS + tx;
                w00 = swp[b0]; w01 = swp[b0 + CS]; w02 = swp[b0 + 2 * CS];
            }
            if (J1) {
                const int b1 = (kd * 9 + (r - 1) * 3) * CS + tx;
                w10 = swp[b1]; w11 = swp[b1 + CS]; w12 = swp[b1 + 2 * CS];
            }

            unsigned long long a = (w0 > 0) ? rowp[(w0 - 1) * CS] : 0ull;
            unsigned long long b = rowp[w0 * CS];
#pragma unroll
            for (int i = 0; i < WPT; i++) {
                const int zw = w0 + i + 1;
                unsigned long long c = (zw < W_) ? rowp[zw * CS] : 0ull;

                if (J0) {
                    acc0[i] = ffma2(a, w00, acc0[i]);
                    acc0[i] = ffma2(b, w01, acc0[i]);
                    acc0[i] = ffma2(c, w02, acc0[i]);
                }
                if (J1) {
                    acc1[i] = ffma2(a, w10, acc1[i]);
                    acc1[i] = ffma2(b, w11, acc1[i]);
                    acc1[i] = ffma2(c, w12, acc1[i]);
                }
                a = b;
                b = c;
            }
        }
    }

    unsigned long long* __restrict__ op =
        reinterpret_cast<unsigned long long*>(out) +
        ((((n * D_ + d) * H_ + h0) * W_ + w0) * CS + tx);
#pragma unroll
    for (int i = 0; i < WPT; i++) {
        op[i * CS] = acc0[i];
        op[W_ * CS + i * CS] = acc1[i];
    }
}

extern "C" void kernel_launch(void* const* d_in, const int* in_sizes, int n_in,
                              void* d_out, int out_size) {
    const float* x = (const float*)d_in[0];
    const float* w = (const float*)d_in[1];
    float* o = (float*)d_out;

    dim3 block(32, 4, 1);                        // 128 threads
    dim3 grid(W_ / WPT, H_ / 8, N_ * D_);        // 14 x 14 x 64
    dwconv3d_kernel<<<grid, block>>>(x, w, o);
}

// round 3
// speedup vs baseline: 1.4244x; 1.0156x over previous
#include <cuda_runtime.h>
#include <cstdint>

// Depthwise 3D conv 3x3x3, SAME, stride 1.
// x: (N=4, D=16, H=112, W=112, C=64) f32, NDHWC
// w: (3,3,3,1,64) f32 -> idx ((kd*3+kh)*3+kw)*64 + c
//
// Thread: 2 channels (f32x2), 8 w-outputs, 2 h-rows.
// R3 changes vs R2:
//  - weight register rotation: J1 taps at row r == J0 taps at row r-1,
//    so only 3 new LDS.64 per row (27 total/thread vs 72).
//  - w-boundary check only on the single unroll iteration that can be OOB.
//  - incremental row pointers.

#define N_  4
#define D_  16
#define H_  112
#define W_  112
#define C_  64
#define WPT 8
#define CS  (C_ / 2)   // 32 ull per spatial position

__device__ __forceinline__ unsigned long long ffma2(unsigned long long a,
                                                    unsigned long long b,
                                                    unsigned long long c) {
    unsigned long long d;
    asm("fma.rn.f32x2 %0, %1, %2, %3;" : "=l"(d) : "l"(a), "l"(b), "l"(c));
    return d;
}

__global__ void __launch_bounds__(128)
dwconv3d_kernel(const float* __restrict__ x,
                const float* __restrict__ wgt,
                float* __restrict__ out) {
    __shared__ float swf[27 * C_];

    const int tid = threadIdx.y * 32 + threadIdx.x;
    for (int i = tid; i < 27 * C_ / 4; i += 128)
        reinterpret_cast<float4*>(swf)[i] =
            reinterpret_cast<const float4*>(wgt)[i];
    __syncthreads();

    const unsigned long long* __restrict__ swp =
        reinterpret_cast<const unsigned long long*>(swf);

    const int tx = threadIdx.x;                       // channel pair 0..31
    const int h0 = blockIdx.y * 8 + threadIdx.y * 2;  // even rows 0..110
    const int w0 = blockIdx.x * WPT;                  // 0..104
    const int nd = blockIdx.z;
    const int n  = nd >> 4;
    const int d  = nd & 15;

    const bool wlo = (w0 > 0);
    const bool whi = (w0 + WPT < W_);   // is zw = w0+8 in range?

    unsigned long long acc0[WPT], acc1[WPT];
#pragma unroll
    for (int i = 0; i < WPT; i++) { acc0[i] = 0ull; acc1[i] = 0ull; }

    const unsigned long long* __restrict__ xp =
        reinterpret_cast<const unsigned long long*>(x);

#pragma unroll
    for (int kd = 0; kd < 3; kd++) {
        const int zd = d + kd - 1;
        if ((unsigned)zd >= D_) continue;

        // pointer to (n, zd, h0-1, w0, tx); advances by one h-row per r
        const unsigned long long* rowp =
            xp + ((((n * D_ + zd) * H_ + (h0 - 1)) * W_ + w0) * CS + tx);

        // weight rotation registers: wa = J0 taps (kd, kh=r), wb = (kd, kh=r-1)
        unsigned long long wa0 = 0, wa1 = 0, wa2 = 0;
        unsigned long long wb0, wb1, wb2;

#pragma unroll
        for (int r = 0; r < 4; r++) {          // zh = h0-1 .. h0+2
            // rotate: previous J0 taps become this row's J1 taps
            wb0 = wa0; wb1 = wa1; wb2 = wa2;
            if (r < 3) {
                const int base = (kd * 9 + r * 3) * CS + tx;
                wa0 = swp[base];
                wa1 = swp[base + CS];
                wa2 = swp[base + 2 * CS];
            }

            const int zh = h0 - 1 + r;
            if ((unsigned)zh < H_) {
                const unsigned long long* __restrict__ p = rowp;

                unsigned long long a = wlo ? p[-CS] : 0ull;
                unsigned long long b = p[0];
#pragma unroll
                for (int i = 0; i < WPT; i++) {
                    unsigned long long c;
                    if (i == WPT - 1)
                        c = whi ? p[WPT * CS] : 0ull;      // zw = w0+8
                    else
                        c = p[(i + 1) * CS];               // always in range

                    if (r <= 2) {                          // output h0, kh=r
                        acc0[i] = ffma2(a, wa0, acc0[i]);
                        acc0[i] = ffma2(b, wa1, acc0[i]);
                        acc0[i] = ffma2(c, wa2, acc0[i]);
                    }
                    if (r >= 1) {                          // output h0+1, kh=r-1
                        acc1[i] = ffma2(a, wb0, acc1[i]);
                        acc1[i] = ffma2(b, wb1, acc1[i]);
                        acc1[i] = ffma2(c, wb2, acc1[i]);
                    }
                    a = b;
                    b = c;
                }
            }
            rowp += W_ * CS;
        }
    }

    unsigned long long* __restrict__ op =
        reinterpret_cast<unsigned long long*>(out) +
        ((((n * D_ + d) * H_ + h0) * W_ + w0) * CS + tx);
#pragma unroll
    for (int i = 0; i < WPT; i++) {
        op[i * CS] = acc0[i];
        op[W_ * CS + i * CS] = acc1[i];
    }
}

extern "C" void kernel_launch(void* const* d_in, const int* in_sizes, int n_in,
                              void* d_out, int out_size) {
    const float* x = (const float*)d_in[0];
    const float* w = (const float*)d_in[1];
    float* o = (float*)d_out;

    dim3 block(32, 4, 1);                        // 128 threads
    dim3 grid(W_ / WPT, H_ / 8, N_ * D_);        // 14 x 14 x 64
    dwconv3d_kernel<<<grid, block>>>(x, w, o);
}

// round 4
// speedup vs baseline: 1.4554x; 1.0218x over previous
#include <cuda_runtime.h>
#include <cstdint>

// Depthwise 3D conv 3x3x3, SAME, stride 1.
// x: (N=4, D=16, H=112, W=112, C=64) f32, NDHWC
// w: (3,3,3,1,64) f32 -> idx ((kd*3+kh)*3+kw)*64 + c
//
// Thread: 2 channels (f32x2), 8 w-outputs, 2 h-rows.
// R4 change vs R3: full-row register preload (rv[10], batched LDG -> MLP=10)
// so the 48 packed FMAs per row run against registers with no load-use stall.

#define N_  4
#define D_  16
#define H_  112
#define W_  112
#define C_  64
#define WPT 8
#define CS  (C_ / 2)   // 32 ull per spatial position

__device__ __forceinline__ unsigned long long ffma2(unsigned long long a,
                                                    unsigned long long b,
                                                    unsigned long long c) {
    unsigned long long d;
    asm("fma.rn.f32x2 %0, %1, %2, %3;" : "=l"(d) : "l"(a), "l"(b), "l"(c));
    return d;
}

__global__ void __launch_bounds__(128)
dwconv3d_kernel(const float* __restrict__ x,
                const float* __restrict__ wgt,
                float* __restrict__ out) {
    __shared__ float swf[27 * C_];

    const int tid = threadIdx.y * 32 + threadIdx.x;
    for (int i = tid; i < 27 * C_ / 4; i += 128)
        reinterpret_cast<float4*>(swf)[i] =
            reinterpret_cast<const float4*>(wgt)[i];
    __syncthreads();

    const unsigned long long* __restrict__ swp =
        reinterpret_cast<const unsigned long long*>(swf);

    const int tx = threadIdx.x;                       // channel pair 0..31
    const int h0 = blockIdx.y * 8 + threadIdx.y * 2;  // even rows 0..110
    const int w0 = blockIdx.x * WPT;                  // 0..104
    const int nd = blockIdx.z;
    const int n  = nd >> 4;
    const int d  = nd & 15;

    const bool wlo = (w0 > 0);
    const bool whi = (w0 + WPT < W_);   // is zw = w0+8 in range?

    unsigned long long acc0[WPT], acc1[WPT];
#pragma unroll
    for (int i = 0; i < WPT; i++) { acc0[i] = 0ull; acc1[i] = 0ull; }

    const unsigned long long* __restrict__ xp =
        reinterpret_cast<const unsigned long long*>(x);

#pragma unroll
    for (int kd = 0; kd < 3; kd++) {
        const int zd = d + kd - 1;
        if ((unsigned)zd >= D_) continue;

        // pointer to (n, zd, h0-1, w0, tx); advances one h-row per r
        const unsigned long long* rowp =
            xp + ((((n * D_ + zd) * H_ + (h0 - 1)) * W_ + w0) * CS + tx);

        // weight rotation: wa = taps (kd, kh=r), wb = (kd, kh=r-1)
        unsigned long long wa0 = 0, wa1 = 0, wa2 = 0;
        unsigned long long wb0, wb1, wb2;

#pragma unroll
        for (int r = 0; r < 4; r++) {          // zh = h0-1 .. h0+2
            wb0 = wa0; wb1 = wa1; wb2 = wa2;
            if (r < 3) {
                const int base = (kd * 9 + r * 3) * CS + tx;
                wa0 = swp[base];
                wa1 = swp[base + CS];
                wa2 = swp[base + 2 * CS];
            }

            const int zh = h0 - 1 + r;
            if ((unsigned)zh < H_) {
                const unsigned long long* __restrict__ p = rowp;

                // --- batched full-row preload: zw = w0-1 .. w0+8 ---
                unsigned long long rv[WPT + 2];
                rv[0] = wlo ? p[-CS] : 0ull;
#pragma unroll
                for (int j = 0; j < WPT; j++)
                    rv[j + 1] = p[j * CS];
                rv[WPT + 1] = whi ? p[WPT * CS] : 0ull;

                // --- register-only FMAs ---
#pragma unroll
                for (int i = 0; i < WPT; i++) {
                    if (r <= 2) {                          // output h0, kh=r
                        acc0[i] = ffma2(rv[i],     wa0, acc0[i]);
                        acc0[i] = ffma2(rv[i + 1], wa1, acc0[i]);
                        acc0[i] = ffma2(rv[i + 2], wa2, acc0[i]);
                    }
                    if (r >= 1) {                          // output h0+1, kh=r-1
                        acc1[i] = ffma2(rv[i],     wb0, acc1[i]);
                        acc1[i] = ffma2(rv[i + 1], wb1, acc1[i]);
                        acc1[i] = ffma2(rv[i + 2], wb2, acc1[i]);
                    }
                }
            }
            rowp += W_ * CS;
        }
    }

    unsigned long long* __restrict__ op =
        reinterpret_cast<unsigned long long*>(out) +
        ((((n * D_ + d) * H_ + h0) * W_ + w0) * CS + tx);
#pragma unroll
    for (int i = 0; i < WPT; i++) {
        op[i * CS] = acc0[i];
        op[W_ * CS + i * CS] = acc1[i];
    }
}

extern "C" void kernel_launch(void* const* d_in, const int* in_sizes, int n_in,
                              void* d_out, int out_size) {
    const float* x = (const float*)d_in[0];
    const float* w = (const float*)d_in[1];
    float* o = (float*)d_out;

    dim3 block(32, 4, 1);                        // 128 threads
    dim3 grid(W_ / WPT, H_ / 8, N_ * D_);        // 14 x 14 x 64
    dwconv3d_kernel<<<grid, block>>>(x, w, o);
}